// round 10
// baseline (speedup 1.0000x reference)
#include <cuda_runtime.h>
#include <cstdint>

// Circuit in linear probability space (one log at the end):
//   p_v = exp(l_v);  s = p1(1-p2) + (1-p1)p2;  t = p1*p2
//   out = log(p0*s + (1-p0)*t)
// Identical to the reference's nested logsumexp (slot-9's -1000 disjunct
// exp-underflows to exactly 0 there too).
__device__ __forceinline__ float circuit_eval(float l0, float l1, float l2) {
    float p0 = __expf(l0);
    float p1 = __expf(l1);
    float p2 = __expf(l2);

    float t  = p1 * p2;
    float a  = __fmaf_rn(-p1, p2, p1);    // p1*(1-p2)
    float b  = __fmaf_rn(-p1, p2, p2);    // (1-p1)*p2
    float s  = a + b;

    float q0 = 1.0f - p0;
    float x  = __fmaf_rn(p0, s, q0 * t);
    return __logf(x);
}

// Warp-private cp.async pipeline: each warp owns a 4-stage ring of
// 128-element tiles (96 float4 per stage). No CTA barriers anywhere --
// warps slip independently; RAW is covered by per-lane wait_group (all
// lanes committed tile k in the same group position) + __syncwarp memory
// ordering; WAR on refill is safe by program order (LDS values already
// consumed by the FFMAs before the refill cp.async issues).
static constexpr int WARPS   = 8;
static constexpr int THREADS = WARPS * 32;
static constexpr int STAGES  = 4;
static constexpr int F4_PER_TILE = 96;     // 128 elems * 3 floats / 4

__global__ void __launch_bounds__(THREADS)
circuit_kernel(const float4* __restrict__ in, float4* __restrict__ out,
               int n_tiles) {
    // 8 warps * 4 stages * 96 * 16B = 48KB (static smem limit, exactly).
    __shared__ __align__(16) float4 buf[WARPS][STAGES][F4_PER_TILE];

    const int warp = threadIdx.x >> 5;
    const int lane = threadIdx.x & 31;
    const int gw     = blockIdx.x * WARPS + warp;   // global warp id
    const int stride = gridDim.x * WARPS;

    // Issue one tile's copies into a stage (3 x 16B cp.async per lane, each
    // instruction coalesced across the warp). Out-of-range tiles commit an
    // empty group to keep per-lane group counts uniform.
    auto issue = [&](int tile, int stage) {
        if (tile < n_tiles) {
            const float4* src = in + (size_t)tile * F4_PER_TILE;
            uint32_t dst = (uint32_t)__cvta_generic_to_shared(&buf[warp][stage][0]);
#pragma unroll
            for (int k = 0; k < 3; k++) {
                asm volatile(
                    "cp.async.cg.shared.global [%0], [%1], 16;"
                    :: "r"(dst + (uint32_t)((k * 32 + lane) * 16)),
                       "l"(src + k * 32 + lane));
            }
        }
        asm volatile("cp.async.commit_group;");
    };

    // Prologue: fill the ring.
#pragma unroll
    for (int s = 0; s < STAGES; s++)
        issue(gw + s * stride, s);

    int stage = 0;
    int ahead = gw + STAGES * stride;
    for (int i = gw; i < n_tiles; i += stride) {
        // Oldest group (tile i) landed for THIS lane; syncwarp orders the
        // other lanes' copies for cross-lane reads below.
        asm volatile("cp.async.wait_group %0;" :: "n"(STAGES - 1));
        __syncwarp();

        // Lane l owns elements 4l..4l+3 = float4s 3l..3l+2 of the tile.
        // 48B lane stride -> banks {12l..12l+3 mod 32}: conflict-free LDS.128.
        float4 a = buf[warp][stage][3 * lane + 0];
        float4 b = buf[warp][stage][3 * lane + 1];
        float4 c = buf[warp][stage][3 * lane + 2];

        float4 r;
        r.x = circuit_eval(a.x, a.y, a.z);
        r.y = circuit_eval(a.w, b.x, b.y);
        r.z = circuit_eval(b.z, b.w, c.x);
        r.w = circuit_eval(c.y, c.z, c.w);

        // Coalesced store (contiguous 512B across the warp).
        out[(size_t)i * 32 + lane] = r;

        // Refill the just-consumed stage (safe: LDS values above were
        // consumed by the FFMA chain before these copies initiate).
        issue(ahead, stage);
        ahead += stride;
        stage = (stage + 1) & (STAGES - 1);
    }
}

// Tail for elements beyond the last full 128-element tile
// (not hit for B=4194304).
__global__ void circuit_tail_kernel(const float* __restrict__ in,
                                    float* __restrict__ out,
                                    int start, int n) {
    int i = start + blockIdx.x * blockDim.x + threadIdx.x;
    if (i >= n) return;
    out[i] = circuit_eval(in[3 * i + 0], in[3 * i + 1], in[3 * i + 2]);
}

extern "C" void kernel_launch(void* const* d_in, const int* in_sizes, int n_in,
                              void* d_out, int out_size) {
    const float* log_probs = (const float*)d_in[0];
    float* out = (float*)d_out;

    int B = out_size;                 // output is (1, B) floats
    int n_tiles = B / 128;            // 128 elements per warp tile

    if (n_tiles > 0) {
        // 4 CTAs/SM by smem (48KB each): one exact wave of 592 CTAs.
        int blocks = 4 * 148;
        int max_blocks = (n_tiles + WARPS - 1) / WARPS;
        if (blocks > max_blocks) blocks = max_blocks;
        circuit_kernel<<<blocks, THREADS>>>(
            (const float4*)log_probs, (float4*)out, n_tiles);
    }
    int done = n_tiles * 128;
    if (done < B) {
        int rem = B - done;
        circuit_tail_kernel<<<(rem + 255) / 256, 256>>>(log_probs, out, done, B);
    }
}

// round 11
// speedup vs baseline: 1.0239x; 1.0239x over previous
#include <cuda_runtime.h>
#include <cstdint>

// Circuit in linear probability space (one log at the end):
//   p_v = exp(l_v);  s = p1(1-p2) + (1-p1)p2;  t = p1*p2
//   out = log(p0*s + (1-p0)*t)
// Identical to the reference's nested logsumexp (slot-9's -1000 disjunct
// exp-underflows to exactly 0 there too).
__device__ __forceinline__ float circuit_eval(float l0, float l1, float l2) {
    float p0 = __expf(l0);
    float p1 = __expf(l1);
    float p2 = __expf(l2);

    float t  = p1 * p2;
    float a  = __fmaf_rn(-p1, p2, p1);    // p1*(1-p2)
    float b  = __fmaf_rn(-p1, p2, p2);    // (1-p1)*p2
    float s  = a + b;

    float q0 = 1.0f - p0;
    float x  = __fmaf_rn(p0, s, q0 * t);
    return __logf(x);
}

// CTA-wide cp.async pipeline (R9 structure, retiled for load balance):
//   THREADS=128, tile = 512 elements (384 float4 in = 3 cp.async/thread,
//   128 float4 out = 1 store/thread), 4 stages x 6.15KB = 24.6KB smem
//   -> 8 CTAs/SM, grid 1184 = one exact wave.
//   8192 tiles / 1184 CTAs = 6.92 -> critical path 7 tiles = 98.8% balance
//   (R9 was 4.61 -> 5 = 92.3%).
static constexpr int THREADS        = 128;
static constexpr int ELEMS_PER_TILE = 512;
static constexpr int F4_PER_TILE    = 384;   // 512 elems * 3 floats / 4
static constexpr int STAGES         = 4;

__global__ void __launch_bounds__(THREADS)
circuit_kernel(const float4* __restrict__ in, float4* __restrict__ out,
               int n_tiles) {
    __shared__ __align__(16) float4 buf[STAGES][F4_PER_TILE];

    const int t      = threadIdx.x;
    const int stride = gridDim.x;

    // Issue one tile's loads into a stage (3 x 16B cp.async per thread,
    // each instruction coalesced across the warp), then commit the group.
    // Out-of-range tiles commit an empty group to keep group counts uniform.
    auto issue = [&](int tile, int stage) {
        if (tile < n_tiles) {
            const float4* src = in + (size_t)tile * F4_PER_TILE;
            uint32_t dst = (uint32_t)__cvta_generic_to_shared(&buf[stage][0]);
#pragma unroll
            for (int k = 0; k < 3; k++) {
                asm volatile(
                    "cp.async.cg.shared.global [%0], [%1], 16;"
                    :: "r"(dst + (uint32_t)((k * THREADS + t) * 16)),
                       "l"(src + k * THREADS + t));
            }
        }
        asm volatile("cp.async.commit_group;");
    };

    // Prologue: fill the pipeline.
#pragma unroll
    for (int s = 0; s < STAGES; s++)
        issue(blockIdx.x + s * stride, s);

    int stage = 0;
    int ahead = blockIdx.x + STAGES * stride;
    for (int i = blockIdx.x; i < n_tiles; i += stride) {
        // Oldest outstanding group (tile i) has landed; make all threads'
        // copies visible to each other.
        asm volatile("cp.async.wait_group %0;" :: "n"(STAGES - 1));
        __syncthreads();

        // Thread t owns elements 4t..4t+3 = float4s 3t..3t+2 of the tile.
        // 48B lane stride -> banks {12l..12l+3 mod 32}: conflict-free LDS.128.
        float4 a = buf[stage][3 * t + 0];
        float4 b = buf[stage][3 * t + 1];
        float4 c = buf[stage][3 * t + 2];

        float4 r;
        r.x = circuit_eval(a.x, a.y, a.z);
        r.y = circuit_eval(a.w, b.x, b.y);
        r.z = circuit_eval(b.z, b.w, c.x);
        r.w = circuit_eval(c.y, c.z, c.w);

        // Coalesced store (contiguous 512B across each warp).
        out[(size_t)i * (F4_PER_TILE / 3) + t] = r;

        // All threads done reading this stage before it is refilled.
        __syncthreads();
        issue(ahead, stage);
        ahead += stride;
        stage = (stage + 1) & (STAGES - 1);
    }
}

// Tail for elements beyond the last full CTA tile (not hit for B=4194304).
__global__ void circuit_tail_kernel(const float* __restrict__ in,
                                    float* __restrict__ out,
                                    int start, int n) {
    int i = start + blockIdx.x * blockDim.x + threadIdx.x;
    if (i >= n) return;
    out[i] = circuit_eval(in[3 * i + 0], in[3 * i + 1], in[3 * i + 2]);
}

extern "C" void kernel_launch(void* const* d_in, const int* in_sizes, int n_in,
                              void* d_out, int out_size) {
    const float* log_probs = (const float*)d_in[0];
    float* out = (float*)d_out;

    int B = out_size;                    // output is (1, B) floats
    int n_tiles = B / ELEMS_PER_TILE;    // 512 elements per CTA tile

    if (n_tiles > 0) {
        // One exact wave: 148 SMs x 8 CTAs (24.6KB smem, 128 thr each).
        int blocks = 8 * 148;
        if (blocks > n_tiles) blocks = n_tiles;
        circuit_kernel<<<blocks, THREADS>>>(
            (const float4*)log_probs, (float4*)out, n_tiles);
    }
    int done = n_tiles * ELEMS_PER_TILE;
    if (done < B) {
        int rem = B - done;
        circuit_tail_kernel<<<(rem + 255) / 256, 256>>>(log_probs, out, done, B);
    }
}